// round 6
// baseline (speedup 1.0000x reference)
#include <cuda_runtime.h>
#include <cuda_fp16.h>
#include <cstdint>

#define MAX_N 50000
#define MAX_E 800000
#define D 128
#define SCAN_B 512
#define MAX_BLK 128   // >= ceil(MAX_N/SCAN_B)

// Scratch (device globals: allocation forbidden in kernel_launch)
__device__ int   g_mode;              // 1 = edge_index is int64, 0 = int32
__device__ int   g_deg[MAX_N];        // edge in-degree (excl self-loop)
__device__ int   g_off[MAX_N];        // CSR row offsets
__device__ int   g_cur[MAX_N];        // fill cursors
__device__ int   g_bsum[MAX_BLK];     // scan block sums
__device__ float g_dis[MAX_N];        // rsqrt(deg+1)
__device__ int   g_src[MAX_E];        // CSR column indices (source nodes)
__device__ uint4 g_h01[MAX_N * 32];   // half2-packed (x0,x1), 4 cols per uint4
__device__ uint4 g_h23[MAX_N * 32];   // half2-packed (x2,x3)

// ---------------------------------------------------------------------------
__global__ void k_detect(const void* ei, int E, int N) {
    if (threadIdx.x == 0 && blockIdx.x == 0) {
        const long long* p64 = (const long long*)ei;
        int n = E < 32 ? E : 32;
        int ok64 = 1;
        for (int i = 0; i < n; i++) {
            long long v = p64[i];
            if (v < 0 || v >= (long long)N) { ok64 = 0; break; }
        }
        g_mode = ok64;
    }
}

__device__ __forceinline__ int edge_at(const void* ei, long long idx, int mode) {
    if (mode) return (int)((const long long*)ei)[idx];
    return ((const int*)ei)[idx];
}

__global__ void k_zero(int N) {
    int i = blockIdx.x * blockDim.x + threadIdx.x;
    if (i < N) g_deg[i] = 0;
}

__global__ void k_count(const void* __restrict__ ei, int E, int N) {
    int e = blockIdx.x * blockDim.x + threadIdx.x;
    if (e >= E) return;
    int mode = g_mode;
    int d = edge_at(ei, (long long)E + e, mode);
    if (d >= 0 && d < N) atomicAdd(&g_deg[d], 1);
}

__global__ void k_scan_block(int N) {
    __shared__ int sm[SCAN_B];
    int i = blockIdx.x * SCAN_B + threadIdx.x;
    int v = (i < N) ? g_deg[i] : 0;
    sm[threadIdx.x] = v;
    __syncthreads();
#pragma unroll
    for (int o = 1; o < SCAN_B; o <<= 1) {
        int t = (threadIdx.x >= o) ? sm[threadIdx.x - o] : 0;
        __syncthreads();
        sm[threadIdx.x] += t;
        __syncthreads();
    }
    if (i < N) g_off[i] = sm[threadIdx.x] - v;   // exclusive
    if (threadIdx.x == SCAN_B - 1) g_bsum[blockIdx.x] = sm[SCAN_B - 1];
}

__global__ void k_scan_sums(int nb) {
    if (threadIdx.x == 0) {
        int acc = 0;
        for (int b = 0; b < nb; b++) { int t = g_bsum[b]; g_bsum[b] = acc; acc += t; }
    }
}

__global__ void k_finalize(int N) {
    int i = blockIdx.x * blockDim.x + threadIdx.x;
    if (i < N) {
        int o = g_off[i] + g_bsum[i / SCAN_B];
        g_off[i] = o;
        g_cur[i] = o;
        g_dis[i] = rsqrtf((float)(g_deg[i] + 1));
    }
}

__global__ void k_fill(const void* __restrict__ ei, int E, int N) {
    int e = blockIdx.x * blockDim.x + threadIdx.x;
    if (e >= E) return;
    int mode = g_mode;
    int s = edge_at(ei, e, mode);
    int d = edge_at(ei, (long long)E + e, mode);
    if (s >= 0 && s < N && d >= 0 && d < N) {
        int pos = atomicAdd(&g_cur[d], 1);
        if (pos >= 0 && pos < E) g_src[pos] = s;
    }
}

// pack 4 fp32 feature sets into two half2 tensors (4 cols per thread)
__global__ void k_cvt(const float* __restrict__ x0, const float* __restrict__ x1,
                      const float* __restrict__ x2, const float* __restrict__ x3,
                      int N) {
    int t = blockIdx.x * blockDim.x + threadIdx.x;
    if (t >= N * 32) return;
    float4 v0 = ((const float4*)x0)[t];
    float4 v1 = ((const float4*)x1)[t];
    float4 v2 = ((const float4*)x2)[t];
    float4 v3 = ((const float4*)x3)[t];
    half2 p01[4] = { __floats2half2_rn(v0.x, v1.x), __floats2half2_rn(v0.y, v1.y),
                     __floats2half2_rn(v0.z, v1.z), __floats2half2_rn(v0.w, v1.w) };
    half2 p23[4] = { __floats2half2_rn(v2.x, v3.x), __floats2half2_rn(v2.y, v3.y),
                     __floats2half2_rn(v2.z, v3.z), __floats2half2_rn(v2.w, v3.w) };
    g_h01[t] = *(const uint4*)p01;
    g_h23[t] = *(const uint4*)p23;
}

// gather-aggregate: one warp per node; neighbors from fp16 pack, self-loop fp32.
__global__ void k_agg(const float* __restrict__ x0, const float* __restrict__ x1,
                      const float* __restrict__ x2, const float* __restrict__ x3,
                      float* __restrict__ out, int N) {
    int gt = blockIdx.x * blockDim.x + threadIdx.x;
    int i = gt >> 5;
    int lane = gt & 31;
    if (i >= N) return;

    float di = g_dis[i];
    float d2 = di * di;
    size_t rv = (size_t)i * 32 + lane;   // float4 / uint4 index

    float acc[4][4];
    {
        float4 v0 = ((const float4*)x0)[rv];
        float4 v1 = ((const float4*)x1)[rv];
        float4 v2 = ((const float4*)x2)[rv];
        float4 v3 = ((const float4*)x3)[rv];
        acc[0][0] = v0.x * d2; acc[0][1] = v0.y * d2; acc[0][2] = v0.z * d2; acc[0][3] = v0.w * d2;
        acc[1][0] = v1.x * d2; acc[1][1] = v1.y * d2; acc[1][2] = v1.z * d2; acc[1][3] = v1.w * d2;
        acc[2][0] = v2.x * d2; acc[2][1] = v2.y * d2; acc[2][2] = v2.z * d2; acc[2][3] = v2.w * d2;
        acc[3][0] = v3.x * d2; acc[3][1] = v3.y * d2; acc[3][2] = v3.z * d2; acc[3][3] = v3.w * d2;
    }

    int beg = g_off[i];
    int end = beg + g_deg[i];
    for (int j = beg; j < end; j++) {
        int s = g_src[j];
        float w = di * g_dis[s];
        size_t sv = (size_t)s * 32 + lane;
        uint4 u01 = g_h01[sv];
        uint4 u23 = g_h23[sv];
        const half2* h01 = (const half2*)&u01;
        const half2* h23 = (const half2*)&u23;
#pragma unroll
        for (int q = 0; q < 4; q++) {
            float2 f01 = __half22float2(h01[q]);
            float2 f23 = __half22float2(h23[q]);
            acc[0][q] = fmaf(f01.x, w, acc[0][q]);
            acc[1][q] = fmaf(f01.y, w, acc[1][q]);
            acc[2][q] = fmaf(f23.x, w, acc[2][q]);
            acc[3][q] = fmaf(f23.y, w, acc[3][q]);
        }
    }

    size_t NN = (size_t)N * 32;
    float4* Y = (float4*)out;
#pragma unroll
    for (int set = 0; set < 4; set++)
        Y[(size_t)set * NN + rv] = make_float4(acc[set][0], acc[set][1],
                                               acc[set][2], acc[set][3]);
}

// ---------------------------------------------------------------------------
// In-place error-split tf32 GEMM: io_s <- io_s @ W_s^T + b_s
// Block 128x128, 8 warps (2x4), warp 64x32; K chunks of 16; A,B split hi/lo.
#define KC 16
#define P20 20   // pitch: g*20 mod 32 distinct for g=0..7 -> conflict-free frags

__device__ __forceinline__ uint32_t f2tf32(float f) {
    uint32_t u;
    asm("cvt.rna.tf32.f32 %0, %1;" : "=r"(u) : "f"(f));
    return u;
}

__device__ __forceinline__ void mma_tf32(float* d, const uint32_t* a, const uint32_t* b) {
    asm volatile(
        "mma.sync.aligned.m16n8k8.row.col.f32.tf32.tf32.f32 "
        "{%0,%1,%2,%3}, {%4,%5,%6,%7}, {%8,%9}, {%0,%1,%2,%3};"
        : "+f"(d[0]), "+f"(d[1]), "+f"(d[2]), "+f"(d[3])
        : "r"(a[0]), "r"(a[1]), "r"(a[2]), "r"(a[3]), "r"(b[0]), "r"(b[1]));
}

__global__ void __launch_bounds__(256, 1) k_gemm(
        const float* __restrict__ W1, const float* __restrict__ b1,
        const float* __restrict__ W2, const float* __restrict__ b2,
        float* io, int N) {
    __shared__ uint32_t AsH[128][P20], AsL[128][P20];
    __shared__ uint32_t WsH[128][P20], WsL[128][P20];

    int set = blockIdx.y;
    const float* Wp = (set == 0 || set == 2) ? W1 : W2;
    const float* bp = (set == 0 || set == 2) ? b1 : b2;
    float* o = io + (size_t)set * N * D;

    int tid = threadIdx.x;
    int m0 = blockIdx.x * 128;
    int warp = tid >> 5, lane = tid & 31;
    int wm = warp >> 2, wn = warp & 3;        // 2 x 4 warp grid
    int g = lane >> 2, c = lane & 3;

    float acc[4][4][4];
#pragma unroll
    for (int mi = 0; mi < 4; mi++)
#pragma unroll
        for (int ni = 0; ni < 4; ni++)
#pragma unroll
            for (int r = 0; r < 4; r++) acc[mi][ni][r] = 0.0f;

    for (int k0 = 0; k0 < D; k0 += KC) {
        for (int idx = tid; idx < 128 * (KC / 4); idx += 256) {
            int m = idx >> 2, k4 = (idx & 3) << 2;
            int gm = m0 + m;
            float4 v = make_float4(0.f, 0.f, 0.f, 0.f);
            if (gm < N) v = *(const float4*)&o[(size_t)gm * D + k0 + k4];
            float vv[4] = {v.x, v.y, v.z, v.w};
#pragma unroll
            for (int q = 0; q < 4; q++) {
                uint32_t hi = f2tf32(vv[q]);
                AsH[m][k4 + q] = hi;
                AsL[m][k4 + q] = f2tf32(vv[q] - __uint_as_float(hi));
            }
        }
        for (int idx = tid; idx < 128 * (KC / 4); idx += 256) {
            int n = idx >> 2, k4 = (idx & 3) << 2;
            float4 v = *(const float4*)&Wp[n * D + k0 + k4];
            float vv[4] = {v.x, v.y, v.z, v.w};
#pragma unroll
            for (int q = 0; q < 4; q++) {
                uint32_t hi = f2tf32(vv[q]);
                WsH[n][k4 + q] = hi;
                WsL[n][k4 + q] = f2tf32(vv[q] - __uint_as_float(hi));
            }
        }
        __syncthreads();

#pragma unroll
        for (int ks = 0; ks < KC / 8; ks++) {
            int kk = ks * 8;
            uint32_t aH[4][4], aL[4][4], bH[4][2], bL[4][2];
#pragma unroll
            for (int mi = 0; mi < 4; mi++) {
                int r = wm * 64 + mi * 16 + g;
                aH[mi][0] = AsH[r][kk + c];     aL[mi][0] = AsL[r][kk + c];
                aH[mi][1] = AsH[r + 8][kk + c]; aL[mi][1] = AsL[r + 8][kk + c];
                aH[mi][2] = AsH[r][kk + c + 4]; aL[mi][2] = AsL[r][kk + c + 4];
                aH[mi][3] = AsH[r + 8][kk + c + 4]; aL[mi][3] = AsL[r + 8][kk + c + 4];
            }
#pragma unroll
            for (int ni = 0; ni < 4; ni++) {
                int n = wn * 32 + ni * 8 + g;
                bH[ni][0] = WsH[n][kk + c];     bL[ni][0] = WsL[n][kk + c];
                bH[ni][1] = WsH[n][kk + c + 4]; bL[ni][1] = WsL[n][kk + c + 4];
            }
#pragma unroll
            for (int mi = 0; mi < 4; mi++)
#pragma unroll
                for (int ni = 0; ni < 4; ni++) {
                    mma_tf32(acc[mi][ni], aH[mi], bL[ni]);
                    mma_tf32(acc[mi][ni], aL[mi], bH[ni]);
                    mma_tf32(acc[mi][ni], aH[mi], bH[ni]);
                }
        }
        __syncthreads();
    }

    // epilogue: add bias, write f32x2 per fragment row
#pragma unroll
    for (int ni = 0; ni < 4; ni++) {
        int cb = wn * 32 + ni * 8 + 2 * c;
        float bv0 = bp[cb], bv1 = bp[cb + 1];
#pragma unroll
        for (int mi = 0; mi < 4; mi++) {
            int r0 = m0 + wm * 64 + mi * 16 + g;
            int r1 = r0 + 8;
            if (r0 < N) {
                float2 v = make_float2(acc[mi][ni][0] + bv0, acc[mi][ni][1] + bv1);
                *(float2*)&o[(size_t)r0 * D + cb] = v;
            }
            if (r1 < N) {
                float2 v = make_float2(acc[mi][ni][2] + bv0, acc[mi][ni][3] + bv1);
                *(float2*)&o[(size_t)r1 * D + cb] = v;
            }
        }
    }
}

// ---------------------------------------------------------------------------
extern "C" void kernel_launch(void* const* d_in, const int* in_sizes, int n_in,
                              void* d_out, int out_size) {
    const float* x0 = (const float*)d_in[0];  // x_r1 (W1)
    const float* x1 = (const float*)d_in[1];  // x_r2 (W2)
    const float* x2 = (const float*)d_in[2];  // x_i1 (W1)
    const float* x3 = (const float*)d_in[3];  // x_i2 (W2)
    const void*  ei = d_in[4];                // edge_index: int64 OR int32
    const float* W1 = (const float*)d_in[5];
    const float* b1 = (const float*)d_in[6];
    const float* W2 = (const float*)d_in[7];
    const float* b2 = (const float*)d_in[8];
    float* out = (float*)d_out;

    int N = in_sizes[0] / D;
    int E = in_sizes[4] / 2;
    int nb_scan = (N + SCAN_B - 1) / SCAN_B;

    // dtype probe + CSR build + normalization (+ fp16 pack)
    k_detect<<<1, 32>>>(ei, E, N);
    k_zero<<<(N + 255) / 256, 256>>>(N);
    k_count<<<(E + 255) / 256, 256>>>(ei, E, N);
    k_cvt<<<(N * 32 + 255) / 256, 256>>>(x0, x1, x2, x3, N);
    k_scan_block<<<nb_scan, SCAN_B>>>(N);
    k_scan_sums<<<1, 32>>>(nb_scan);
    k_finalize<<<(N + 255) / 256, 256>>>(N);
    k_fill<<<(E + 255) / 256, 256>>>(ei, E, N);

    // gather-aggregate into d_out (scratch)
    {
        long long threads = (long long)N * 32;
        int blocks = (int)((threads + 255) / 256);
        k_agg<<<blocks, 256>>>(x0, x1, x2, x3, out, N);
    }

    // in-place tensor-core GEMM + bias (error-split tf32)
    {
        dim3 grid((N + 127) / 128, 4);
        k_gemm<<<grid, 256>>>(W1, b1, W2, b2, out, N);
    }
}

// round 7
// speedup vs baseline: 1.3995x; 1.3995x over previous
#include <cuda_runtime.h>
#include <cuda_fp16.h>
#include <cstdint>

#define MAX_N 50000
#define MAX_E 800000
#define D 128
#define SCAN_B 512
#define MAX_BLK 128   // >= ceil(MAX_N/SCAN_B)

// Scratch (device globals: allocation forbidden in kernel_launch)
__device__ int   g_mode;              // 1 = edge_index is int64, 0 = int32
__device__ int   g_deg[MAX_N];        // edge in-degree (excl self-loop)
__device__ int   g_off[MAX_N];        // CSR row offsets
__device__ int   g_cur[MAX_N];        // fill cursors
__device__ int   g_bsum[MAX_BLK];     // scan block sums
__device__ float g_dis[MAX_N];        // rsqrt(deg+1)
__device__ int   g_src[MAX_E];        // CSR column indices (source nodes)
__device__ uint4 g_h01[MAX_N * 32];   // half2-packed (x0,x1), 4 cols per uint4
__device__ uint4 g_h23[MAX_N * 32];   // half2-packed (x2,x3)

// ---------------------------------------------------------------------------
__global__ void k_detect(const void* ei, int E, int N) {
    if (threadIdx.x == 0 && blockIdx.x == 0) {
        const long long* p64 = (const long long*)ei;
        int n = E < 32 ? E : 32;
        int ok64 = 1;
        for (int i = 0; i < n; i++) {
            long long v = p64[i];
            if (v < 0 || v >= (long long)N) { ok64 = 0; break; }
        }
        g_mode = ok64;
    }
}

__device__ __forceinline__ int edge_at(const void* ei, long long idx, int mode) {
    if (mode) return (int)((const long long*)ei)[idx];
    return ((const int*)ei)[idx];
}

__global__ void k_zero(int N) {
    int i = blockIdx.x * blockDim.x + threadIdx.x;
    if (i < N) g_deg[i] = 0;
}

__global__ void k_count(const void* __restrict__ ei, int E, int N) {
    int e = blockIdx.x * blockDim.x + threadIdx.x;
    if (e >= E) return;
    int mode = g_mode;
    int d = edge_at(ei, (long long)E + e, mode);
    if (d >= 0 && d < N) atomicAdd(&g_deg[d], 1);
}

__global__ void k_scan_block(int N) {
    __shared__ int sm[SCAN_B];
    int i = blockIdx.x * SCAN_B + threadIdx.x;
    int v = (i < N) ? g_deg[i] : 0;
    sm[threadIdx.x] = v;
    __syncthreads();
#pragma unroll
    for (int o = 1; o < SCAN_B; o <<= 1) {
        int t = (threadIdx.x >= o) ? sm[threadIdx.x - o] : 0;
        __syncthreads();
        sm[threadIdx.x] += t;
        __syncthreads();
    }
    if (i < N) g_off[i] = sm[threadIdx.x] - v;   // exclusive
    if (threadIdx.x == SCAN_B - 1) g_bsum[blockIdx.x] = sm[SCAN_B - 1];
}

__global__ void k_scan_sums(int nb) {
    if (threadIdx.x == 0) {
        int acc = 0;
        for (int b = 0; b < nb; b++) { int t = g_bsum[b]; g_bsum[b] = acc; acc += t; }
    }
}

__global__ void k_finalize(int N) {
    int i = blockIdx.x * blockDim.x + threadIdx.x;
    if (i < N) {
        int o = g_off[i] + g_bsum[i / SCAN_B];
        g_off[i] = o;
        g_cur[i] = o;
        g_dis[i] = rsqrtf((float)(g_deg[i] + 1));
    }
}

__global__ void k_fill(const void* __restrict__ ei, int E, int N) {
    int e = blockIdx.x * blockDim.x + threadIdx.x;
    if (e >= E) return;
    int mode = g_mode;
    int s = edge_at(ei, e, mode);
    int d = edge_at(ei, (long long)E + e, mode);
    if (s >= 0 && s < N && d >= 0 && d < N) {
        int pos = atomicAdd(&g_cur[d], 1);
        if (pos >= 0 && pos < E) g_src[pos] = s;
    }
}

// pack 4 fp32 feature sets into two half2 tensors (4 cols per thread)
__global__ void k_cvt(const float* __restrict__ x0, const float* __restrict__ x1,
                      const float* __restrict__ x2, const float* __restrict__ x3,
                      int N) {
    int t = blockIdx.x * blockDim.x + threadIdx.x;
    if (t >= N * 32) return;
    float4 v0 = ((const float4*)x0)[t];
    float4 v1 = ((const float4*)x1)[t];
    float4 v2 = ((const float4*)x2)[t];
    float4 v3 = ((const float4*)x3)[t];
    half2 p01[4] = { __floats2half2_rn(v0.x, v1.x), __floats2half2_rn(v0.y, v1.y),
                     __floats2half2_rn(v0.z, v1.z), __floats2half2_rn(v0.w, v1.w) };
    half2 p23[4] = { __floats2half2_rn(v2.x, v3.x), __floats2half2_rn(v2.y, v3.y),
                     __floats2half2_rn(v2.z, v3.z), __floats2half2_rn(v2.w, v3.w) };
    g_h01[t] = *(const uint4*)p01;
    g_h23[t] = *(const uint4*)p23;
}

// gather-aggregate: one warp per node; neighbors from fp16 pack, self-loop fp32.
__global__ void k_agg(const float* __restrict__ x0, const float* __restrict__ x1,
                      const float* __restrict__ x2, const float* __restrict__ x3,
                      float* __restrict__ out, int N) {
    int gt = blockIdx.x * blockDim.x + threadIdx.x;
    int i = gt >> 5;
    int lane = gt & 31;
    if (i >= N) return;

    float di = g_dis[i];
    float d2 = di * di;
    size_t rv = (size_t)i * 32 + lane;   // float4 / uint4 index

    float acc[4][4];
    {
        float4 v0 = ((const float4*)x0)[rv];
        float4 v1 = ((const float4*)x1)[rv];
        float4 v2 = ((const float4*)x2)[rv];
        float4 v3 = ((const float4*)x3)[rv];
        acc[0][0] = v0.x * d2; acc[0][1] = v0.y * d2; acc[0][2] = v0.z * d2; acc[0][3] = v0.w * d2;
        acc[1][0] = v1.x * d2; acc[1][1] = v1.y * d2; acc[1][2] = v1.z * d2; acc[1][3] = v1.w * d2;
        acc[2][0] = v2.x * d2; acc[2][1] = v2.y * d2; acc[2][2] = v2.z * d2; acc[2][3] = v2.w * d2;
        acc[3][0] = v3.x * d2; acc[3][1] = v3.y * d2; acc[3][2] = v3.z * d2; acc[3][3] = v3.w * d2;
    }

    int beg = g_off[i];
    int end = beg + g_deg[i];
    for (int j = beg; j < end; j++) {
        int s = g_src[j];
        float w = di * g_dis[s];
        size_t sv = (size_t)s * 32 + lane;
        uint4 u01 = g_h01[sv];
        uint4 u23 = g_h23[sv];
        const half2* h01 = (const half2*)&u01;
        const half2* h23 = (const half2*)&u23;
#pragma unroll
        for (int q = 0; q < 4; q++) {
            float2 f01 = __half22float2(h01[q]);
            float2 f23 = __half22float2(h23[q]);
            acc[0][q] = fmaf(f01.x, w, acc[0][q]);
            acc[1][q] = fmaf(f01.y, w, acc[1][q]);
            acc[2][q] = fmaf(f23.x, w, acc[2][q]);
            acc[3][q] = fmaf(f23.y, w, acc[3][q]);
        }
    }

    size_t NN = (size_t)N * 32;
    float4* Y = (float4*)out;
#pragma unroll
    for (int set = 0; set < 4; set++)
        Y[(size_t)set * NN + rv] = make_float4(acc[set][0], acc[set][1],
                                               acc[set][2], acc[set][3]);
}

// ---------------------------------------------------------------------------
// In-place GEMM on tensor cores: io_s <- io_s @ W_s^T + b_s  (tf32 mma, f32 acc)
// Block 128(M)x128(N), 8 warps as 2(M)x4(N) -> warp tile 64x32.
// K chunked by 32; operands tf32-converted at smem-store time.
#define KC 32
#define APITCH 36   // (4g+c)%32 -> conflict-free fragment loads

__device__ __forceinline__ uint32_t f2tf32(float f) {
    uint32_t u;
    asm("cvt.rna.tf32.f32 %0, %1;" : "=r"(u) : "f"(f));
    return u;
}

__device__ __forceinline__ void mma_tf32(float* d, const uint32_t* a, const uint32_t* b) {
    asm volatile(
        "mma.sync.aligned.m16n8k8.row.col.f32.tf32.tf32.f32 "
        "{%0,%1,%2,%3}, {%4,%5,%6,%7}, {%8,%9}, {%0,%1,%2,%3};"
        : "+f"(d[0]), "+f"(d[1]), "+f"(d[2]), "+f"(d[3])
        : "r"(a[0]), "r"(a[1]), "r"(a[2]), "r"(a[3]), "r"(b[0]), "r"(b[1]));
}

__global__ void __launch_bounds__(256) k_gemm(
        const float* __restrict__ W1, const float* __restrict__ b1,
        const float* __restrict__ W2, const float* __restrict__ b2,
        float* io, int N) {
    __shared__ uint32_t As[128][APITCH];  // y tile  [m][k], tf32 bits
    __shared__ uint32_t Ws[128][APITCH];  // W tile  [n][k], tf32 bits (B col-major)

    int set = blockIdx.y;
    const float* Wp = (set == 0 || set == 2) ? W1 : W2;
    const float* bp = (set == 0 || set == 2) ? b1 : b2;
    float* o = io + (size_t)set * N * D;

    int tid = threadIdx.x;
    int m0 = blockIdx.x * 128;
    int warp = tid >> 5, lane = tid & 31;
    int wm = warp >> 2, wn = warp & 3;        // 2 x 4 warp grid
    int g = lane >> 2, c = lane & 3;

    float acc[4][4][4];
#pragma unroll
    for (int mi = 0; mi < 4; mi++)
#pragma unroll
        for (int ni = 0; ni < 4; ni++)
#pragma unroll
            for (int r = 0; r < 4; r++) acc[mi][ni][r] = 0.0f;

    for (int k0 = 0; k0 < D; k0 += KC) {
        // stage y tile (guarded) and W tile, converting to tf32
        for (int idx = tid; idx < 128 * (KC / 4); idx += 256) {
            int m = idx >> 3, k4 = (idx & 7) << 2;
            int gm = m0 + m;
            float4 v = make_float4(0.f, 0.f, 0.f, 0.f);
            if (gm < N) v = *(const float4*)&o[(size_t)gm * D + k0 + k4];
            As[m][k4 + 0] = f2tf32(v.x);
            As[m][k4 + 1] = f2tf32(v.y);
            As[m][k4 + 2] = f2tf32(v.z);
            As[m][k4 + 3] = f2tf32(v.w);
        }
        for (int idx = tid; idx < 128 * (KC / 4); idx += 256) {
            int n = idx >> 3, k4 = (idx & 7) << 2;
            float4 v = *(const float4*)&Wp[n * D + k0 + k4];
            Ws[n][k4 + 0] = f2tf32(v.x);
            Ws[n][k4 + 1] = f2tf32(v.y);
            Ws[n][k4 + 2] = f2tf32(v.z);
            Ws[n][k4 + 3] = f2tf32(v.w);
        }
        __syncthreads();

#pragma unroll
        for (int ks = 0; ks < KC / 8; ks++) {
            int kk = ks * 8;
            uint32_t a[4][4], b[4][2];
#pragma unroll
            for (int mi = 0; mi < 4; mi++) {
                int r = wm * 64 + mi * 16 + g;
                a[mi][0] = As[r][kk + c];
                a[mi][1] = As[r + 8][kk + c];
                a[mi][2] = As[r][kk + c + 4];
                a[mi][3] = As[r + 8][kk + c + 4];
            }
#pragma unroll
            for (int ni = 0; ni < 4; ni++) {
                int n = wn * 32 + ni * 8 + g;
                b[ni][0] = Ws[n][kk + c];
                b[ni][1] = Ws[n][kk + c + 4];
            }
#pragma unroll
            for (int mi = 0; mi < 4; mi++)
#pragma unroll
                for (int ni = 0; ni < 4; ni++)
                    mma_tf32(acc[mi][ni], a[mi], b[ni]);
        }
        __syncthreads();
    }

    // epilogue: add bias, write f32x2 per fragment row
#pragma unroll
    for (int ni = 0; ni < 4; ni++) {
        int cb = wn * 32 + ni * 8 + 2 * c;
        float bv0 = bp[cb], bv1 = bp[cb + 1];
#pragma unroll
        for (int mi = 0; mi < 4; mi++) {
            int r0 = m0 + wm * 64 + mi * 16 + g;
            int r1 = r0 + 8;
            if (r0 < N) {
                float2 v = make_float2(acc[mi][ni][0] + bv0, acc[mi][ni][1] + bv1);
                *(float2*)&o[(size_t)r0 * D + cb] = v;
            }
            if (r1 < N) {
                float2 v = make_float2(acc[mi][ni][2] + bv0, acc[mi][ni][3] + bv1);
                *(float2*)&o[(size_t)r1 * D + cb] = v;
            }
        }
    }
}

// ---------------------------------------------------------------------------
extern "C" void kernel_launch(void* const* d_in, const int* in_sizes, int n_in,
                              void* d_out, int out_size) {
    const float* x0 = (const float*)d_in[0];  // x_r1 (W1)
    const float* x1 = (const float*)d_in[1];  // x_r2 (W2)
    const float* x2 = (const float*)d_in[2];  // x_i1 (W1)
    const float* x3 = (const float*)d_in[3];  // x_i2 (W2)
    const void*  ei = d_in[4];                // edge_index: int64 OR int32
    const float* W1 = (const float*)d_in[5];
    const float* b1 = (const float*)d_in[6];
    const float* W2 = (const float*)d_in[7];
    const float* b2 = (const float*)d_in[8];
    float* out = (float*)d_out;

    int N = in_sizes[0] / D;
    int E = in_sizes[4] / 2;
    int nb_scan = (N + SCAN_B - 1) / SCAN_B;

    // dtype probe + CSR build + normalization (+ fp16 pack)
    k_detect<<<1, 32>>>(ei, E, N);
    k_zero<<<(N + 255) / 256, 256>>>(N);
    k_count<<<(E + 255) / 256, 256>>>(ei, E, N);
    k_cvt<<<(N * 32 + 255) / 256, 256>>>(x0, x1, x2, x3, N);
    k_scan_block<<<nb_scan, SCAN_B>>>(N);
    k_scan_sums<<<1, 32>>>(nb_scan);
    k_finalize<<<(N + 255) / 256, 256>>>(N);
    k_fill<<<(E + 255) / 256, 256>>>(ei, E, N);

    // gather-aggregate into d_out (scratch)
    {
        long long threads = (long long)N * 32;
        int blocks = (int)((threads + 255) / 256);
        k_agg<<<blocks, 256>>>(x0, x1, x2, x3, out, N);
    }

    // in-place tensor-core GEMM + bias
    {
        dim3 grid((N + 127) / 128, 4);
        k_gemm<<<grid, 256>>>(W1, b1, W2, b2, out, N);
    }
}

// round 8
// speedup vs baseline: 1.4914x; 1.0657x over previous
#include <cuda_runtime.h>
#include <cuda_fp16.h>
#include <cstdint>

#define MAX_N 50000
#define MAX_E 800000
#define D 128
#define SCAN_B 512
#define MAX_BLK 128   // >= ceil(MAX_N/SCAN_B)

// Scratch (device globals: allocation forbidden in kernel_launch)
__device__ int    g_mode;             // 1 = edge_index is int64, 0 = int32
__device__ int    g_deg[MAX_N];       // edge in-degree (excl self-loop)
__device__ int    g_off[MAX_N];       // CSR row offsets
__device__ int    g_cur[MAX_N];       // fill cursors
__device__ int    g_bsum[MAX_BLK];    // scan block sums
__device__ float  g_dis[MAX_N];       // rsqrt(deg+1)
__device__ int    g_src[MAX_E];       // CSR column indices (source nodes)
__device__ __half g_h[4ull * MAX_N * D];  // h = x @ W^T in fp16, per set

// ---------------------------------------------------------------------------
__global__ void k_detect(const void* ei, int E, int N) {
    if (threadIdx.x == 0 && blockIdx.x == 0) {
        const long long* p64 = (const long long*)ei;
        int n = E < 32 ? E : 32;
        int ok64 = 1;
        for (int i = 0; i < n; i++) {
            long long v = p64[i];
            if (v < 0 || v >= (long long)N) { ok64 = 0; break; }
        }
        g_mode = ok64;
    }
}

__device__ __forceinline__ int edge_at(const void* ei, long long idx, int mode) {
    if (mode) return (int)((const long long*)ei)[idx];
    return ((const int*)ei)[idx];
}

__global__ void k_zero(int N) {
    int i = blockIdx.x * blockDim.x + threadIdx.x;
    if (i < N) g_deg[i] = 0;
}

__global__ void k_count(const void* __restrict__ ei, int E, int N) {
    int e = blockIdx.x * blockDim.x + threadIdx.x;
    if (e >= E) return;
    int mode = g_mode;
    int d = edge_at(ei, (long long)E + e, mode);
    if (d >= 0 && d < N) atomicAdd(&g_deg[d], 1);
}

__global__ void k_scan_block(int N) {
    __shared__ int sm[SCAN_B];
    int i = blockIdx.x * SCAN_B + threadIdx.x;
    int v = (i < N) ? g_deg[i] : 0;
    sm[threadIdx.x] = v;
    __syncthreads();
#pragma unroll
    for (int o = 1; o < SCAN_B; o <<= 1) {
        int t = (threadIdx.x >= o) ? sm[threadIdx.x - o] : 0;
        __syncthreads();
        sm[threadIdx.x] += t;
        __syncthreads();
    }
    if (i < N) g_off[i] = sm[threadIdx.x] - v;   // exclusive
    if (threadIdx.x == SCAN_B - 1) g_bsum[blockIdx.x] = sm[SCAN_B - 1];
}

__global__ void k_scan_sums(int nb) {
    if (threadIdx.x == 0) {
        int acc = 0;
        for (int b = 0; b < nb; b++) { int t = g_bsum[b]; g_bsum[b] = acc; acc += t; }
    }
}

__global__ void k_finalize(int N) {
    int i = blockIdx.x * blockDim.x + threadIdx.x;
    if (i < N) {
        int o = g_off[i] + g_bsum[i / SCAN_B];
        g_off[i] = o;
        g_cur[i] = o;
        g_dis[i] = rsqrtf((float)(g_deg[i] + 1));
    }
}

__global__ void k_fill(const void* __restrict__ ei, int E, int N) {
    int e = blockIdx.x * blockDim.x + threadIdx.x;
    if (e >= E) return;
    int mode = g_mode;
    int s = edge_at(ei, e, mode);
    int d = edge_at(ei, (long long)E + e, mode);
    if (s >= 0 && s < N && d >= 0 && d < N) {
        int pos = atomicAdd(&g_cur[d], 1);
        if (pos >= 0 && pos < E) g_src[pos] = s;
    }
}

// ---------------------------------------------------------------------------
// GEMM (no bias): g_h[set] = fp16( x_set @ W^T )   (tf32 mma, f32 acc)
// Block 128(M)x128(N), 8 warps as 2(M)x4(N), warp 64x32, K chunks of 32.
#define KC 32
#define APITCH 36   // (4g+c)%32 -> conflict-free fragment loads

__device__ __forceinline__ uint32_t f2tf32(float f) {
    uint32_t u;
    asm("cvt.rna.tf32.f32 %0, %1;" : "=r"(u) : "f"(f));
    return u;
}

__device__ __forceinline__ void mma_tf32(float* d, const uint32_t* a, const uint32_t* b) {
    asm volatile(
        "mma.sync.aligned.m16n8k8.row.col.f32.tf32.tf32.f32 "
        "{%0,%1,%2,%3}, {%4,%5,%6,%7}, {%8,%9}, {%0,%1,%2,%3};"
        : "+f"(d[0]), "+f"(d[1]), "+f"(d[2]), "+f"(d[3])
        : "r"(a[0]), "r"(a[1]), "r"(a[2]), "r"(a[3]), "r"(b[0]), "r"(b[1]));
}

__global__ void __launch_bounds__(256) k_gemm(
        const float* __restrict__ x0, const float* __restrict__ x1,
        const float* __restrict__ x2, const float* __restrict__ x3,
        const float* __restrict__ W1, const float* __restrict__ W2,
        int N) {
    __shared__ uint32_t As[128][APITCH];  // x tile [m][k], tf32 bits
    __shared__ uint32_t Ws[128][APITCH];  // W tile [n][k], tf32 bits

    int set = blockIdx.y;
    const float* xp = (set == 0) ? x0 : (set == 1) ? x1 : (set == 2) ? x2 : x3;
    const float* Wp = (set == 0 || set == 2) ? W1 : W2;
    __half* h = g_h + (size_t)set * N * D;

    int tid = threadIdx.x;
    int m0 = blockIdx.x * 128;
    int warp = tid >> 5, lane = tid & 31;
    int wm = warp >> 2, wn = warp & 3;        // 2 x 4 warp grid
    int g = lane >> 2, c = lane & 3;

    float acc[4][4][4];
#pragma unroll
    for (int mi = 0; mi < 4; mi++)
#pragma unroll
        for (int ni = 0; ni < 4; ni++)
#pragma unroll
            for (int r = 0; r < 4; r++) acc[mi][ni][r] = 0.0f;

    for (int k0 = 0; k0 < D; k0 += KC) {
        for (int idx = tid; idx < 128 * (KC / 4); idx += 256) {
            int m = idx >> 3, k4 = (idx & 7) << 2;
            int gm = m0 + m;
            float4 v = make_float4(0.f, 0.f, 0.f, 0.f);
            if (gm < N) v = *(const float4*)&xp[(size_t)gm * D + k0 + k4];
            As[m][k4 + 0] = f2tf32(v.x);
            As[m][k4 + 1] = f2tf32(v.y);
            As[m][k4 + 2] = f2tf32(v.z);
            As[m][k4 + 3] = f2tf32(v.w);
        }
        for (int idx = tid; idx < 128 * (KC / 4); idx += 256) {
            int n = idx >> 3, k4 = (idx & 7) << 2;
            float4 v = *(const float4*)&Wp[n * D + k0 + k4];
            Ws[n][k4 + 0] = f2tf32(v.x);
            Ws[n][k4 + 1] = f2tf32(v.y);
            Ws[n][k4 + 2] = f2tf32(v.z);
            Ws[n][k4 + 3] = f2tf32(v.w);
        }
        __syncthreads();

#pragma unroll
        for (int ks = 0; ks < KC / 8; ks++) {
            int kk = ks * 8;
            uint32_t a[4][4], b[4][2];
#pragma unroll
            for (int mi = 0; mi < 4; mi++) {
                int r = wm * 64 + mi * 16 + g;
                a[mi][0] = As[r][kk + c];
                a[mi][1] = As[r + 8][kk + c];
                a[mi][2] = As[r][kk + c + 4];
                a[mi][3] = As[r + 8][kk + c + 4];
            }
#pragma unroll
            for (int ni = 0; ni < 4; ni++) {
                int n = wn * 32 + ni * 8 + g;
                b[ni][0] = Ws[n][kk + c];
                b[ni][1] = Ws[n][kk + c + 4];
            }
#pragma unroll
            for (int mi = 0; mi < 4; mi++)
#pragma unroll
                for (int ni = 0; ni < 4; ni++)
                    mma_tf32(acc[mi][ni], a[mi], b[ni]);
        }
        __syncthreads();
    }

    // epilogue: convert to fp16, write half2 per fragment pair
#pragma unroll
    for (int ni = 0; ni < 4; ni++) {
        int cb = wn * 32 + ni * 8 + 2 * c;
#pragma unroll
        for (int mi = 0; mi < 4; mi++) {
            int r0 = m0 + wm * 64 + mi * 16 + g;
            int r1 = r0 + 8;
            if (r0 < N)
                *(__half2*)&h[(size_t)r0 * D + cb] =
                    __floats2half2_rn(acc[mi][ni][0], acc[mi][ni][1]);
            if (r1 < N)
                *(__half2*)&h[(size_t)r1 * D + cb] =
                    __floats2half2_rn(acc[mi][ni][2], acc[mi][ni][3]);
        }
    }
}

// ---------------------------------------------------------------------------
// Aggregation: out_s[i] = sum_j norm_ij * h_s[j]  + b_s   (fp32 accumulate)
// One warp per node. Lanes 0-15 handle sets {0,1}, lanes 16-31 sets {2,3};
// each lane owns 8 consecutive columns (one uint4 = 8 halves per set).
__global__ void k_agg(const float* __restrict__ b1, const float* __restrict__ b2,
                      float* __restrict__ out, int N) {
    int gt = blockIdx.x * blockDim.x + threadIdx.x;
    int i = gt >> 5;
    int lane = gt & 31;
    if (i >= N) return;

    int pair = lane >> 4;        // 0 -> sets 0,1 ; 1 -> sets 2,3
    int cp = lane & 15;          // uint4 column index (8 halves)
    int setA = pair * 2;         // 0 or 2  (bias b1)
    int setB = setA + 1;         // 1 or 3  (bias b2)

    const uint4* HA = (const uint4*)(g_h + (size_t)setA * N * D);
    const uint4* HB = (const uint4*)(g_h + (size_t)setB * N * D);

    float di = g_dis[i];
    float d2 = di * di;

    float accA[8], accB[8];
    {   // self-loop term
        uint4 ua = HA[(size_t)i * 16 + cp];
        uint4 ub = HB[(size_t)i * 16 + cp];
        const half2* pa = (const half2*)&ua;
        const half2* pb = (const half2*)&ub;
#pragma unroll
        for (int q = 0; q < 4; q++) {
            float2 fa = __half22float2(pa[q]);
            float2 fb = __half22float2(pb[q]);
            accA[2 * q] = fa.x * d2; accA[2 * q + 1] = fa.y * d2;
            accB[2 * q] = fb.x * d2; accB[2 * q + 1] = fb.y * d2;
        }
    }

    int beg = g_off[i];
    int end = beg + g_deg[i];
    for (int j = beg; j < end; j++) {
        int s = g_src[j];
        float w = di * g_dis[s];
        uint4 ua = HA[(size_t)s * 16 + cp];
        uint4 ub = HB[(size_t)s * 16 + cp];
        const half2* pa = (const half2*)&ua;
        const half2* pb = (const half2*)&ub;
#pragma unroll
        for (int q = 0; q < 4; q++) {
            float2 fa = __half22float2(pa[q]);
            float2 fb = __half22float2(pb[q]);
            accA[2 * q]     = fmaf(fa.x, w, accA[2 * q]);
            accA[2 * q + 1] = fmaf(fa.y, w, accA[2 * q + 1]);
            accB[2 * q]     = fmaf(fb.x, w, accB[2 * q]);
            accB[2 * q + 1] = fmaf(fb.y, w, accB[2 * q + 1]);
        }
    }

    // bias + write
    int col = cp * 8;
    float4 bA0 = *(const float4*)&b1[col];
    float4 bA1 = *(const float4*)&b1[col + 4];
    float4 bB0 = *(const float4*)&b2[col];
    float4 bB1 = *(const float4*)&b2[col + 4];

    float* oA = out + (size_t)setA * N * D + (size_t)i * D + col;
    float* oB = out + (size_t)setB * N * D + (size_t)i * D + col;
    *(float4*)oA       = make_float4(accA[0] + bA0.x, accA[1] + bA0.y,
                                     accA[2] + bA0.z, accA[3] + bA0.w);
    *(float4*)(oA + 4) = make_float4(accA[4] + bA1.x, accA[5] + bA1.y,
                                     accA[6] + bA1.z, accA[7] + bA1.w);
    *(float4*)oB       = make_float4(accB[0] + bB0.x, accB[1] + bB0.y,
                                     accB[2] + bB0.z, accB[3] + bB0.w);
    *(float4*)(oB + 4) = make_float4(accB[4] + bB1.x, accB[5] + bB1.y,
                                     accB[6] + bB1.z, accB[7] + bB1.w);
}

// ---------------------------------------------------------------------------
extern "C" void kernel_launch(void* const* d_in, const int* in_sizes, int n_in,
                              void* d_out, int out_size) {
    const float* x0 = (const float*)d_in[0];  // x_r1 (W1,b1)
    const float* x1 = (const float*)d_in[1];  // x_r2 (W2,b2)
    const float* x2 = (const float*)d_in[2];  // x_i1 (W1,b1)
    const float* x3 = (const float*)d_in[3];  // x_i2 (W2,b2)
    const void*  ei = d_in[4];                // edge_index: int64 OR int32
    const float* W1 = (const float*)d_in[5];
    const float* b1 = (const float*)d_in[6];
    const float* W2 = (const float*)d_in[7];
    const float* b2 = (const float*)d_in[8];
    float* out = (float*)d_out;

    int N = in_sizes[0] / D;
    int E = in_sizes[4] / 2;
    int nb_scan = (N + SCAN_B - 1) / SCAN_B;

    // dtype probe + CSR build + normalization
    k_detect<<<1, 32>>>(ei, E, N);
    k_zero<<<(N + 255) / 256, 256>>>(N);
    k_count<<<(E + 255) / 256, 256>>>(ei, E, N);

    // GEMM first (independent of CSR): h = fp16(x @ W^T), no bias
    {
        dim3 grid((N + 127) / 128, 4);
        k_gemm<<<grid, 256>>>(x0, x1, x2, x3, W1, W2, N);
    }

    k_scan_block<<<nb_scan, SCAN_B>>>(N);
    k_scan_sums<<<1, 32>>>(nb_scan);
    k_finalize<<<(N + 255) / 256, 256>>>(N);
    k_fill<<<(E + 255) / 256, 256>>>(ei, E, N);

    // aggregate fp16 h with fp32 accumulation, add bias, write out
    {
        long long threads = (long long)N * 32;
        int blocks = (int)((threads + 255) / 256);
        k_agg<<<blocks, 256>>>(b1, b2, out, N);
    }
}

// round 9
// speedup vs baseline: 1.7858x; 1.1974x over previous
#include <cuda_runtime.h>
#include <cuda_fp16.h>
#include <cstdint>

#define MAX_N 50000
#define MAX_E 800000
#define D 128
#define SCAN_B 512
#define MAX_BLK 128   // >= ceil(MAX_N/SCAN_B)

// Scratch (device globals: allocation forbidden in kernel_launch)
__device__ int    g_mode;             // 1 = edge_index is int64, 0 = int32
__device__ int    g_deg[MAX_N];       // edge in-degree (excl self-loop)
__device__ int    g_off[MAX_N];       // CSR row offsets
__device__ int    g_cur[MAX_N];       // fill cursors
__device__ int    g_bsum[MAX_BLK];    // scan block sums
__device__ float  g_dis[MAX_N];       // rsqrt(deg+1)
__device__ int    g_src[MAX_E];       // CSR column indices (source nodes)
__device__ __half g_h[4ull * MAX_N * D];  // h = x @ W^T in fp16, per set

// ---------------------------------------------------------------------------
__global__ void k_detect(const void* ei, int E, int N) {
    if (threadIdx.x == 0 && blockIdx.x == 0) {
        const long long* p64 = (const long long*)ei;
        int n = E < 32 ? E : 32;
        int ok64 = 1;
        for (int i = 0; i < n; i++) {
            long long v = p64[i];
            if (v < 0 || v >= (long long)N) { ok64 = 0; break; }
        }
        g_mode = ok64;
    }
}

__device__ __forceinline__ int edge_at(const void* ei, long long idx, int mode) {
    if (mode) return (int)((const long long*)ei)[idx];
    return ((const int*)ei)[idx];
}

__global__ void k_zero(int N) {
    int i = blockIdx.x * blockDim.x + threadIdx.x;
    if (i < N) g_deg[i] = 0;
}

__global__ void k_count(const void* __restrict__ ei, int E, int N) {
    int e = blockIdx.x * blockDim.x + threadIdx.x;
    if (e >= E) return;
    int mode = g_mode;
    int d = edge_at(ei, (long long)E + e, mode);
    if (d >= 0 && d < N) atomicAdd(&g_deg[d], 1);
}

__global__ void k_scan_block(int N) {
    __shared__ int sm[SCAN_B];
    int i = blockIdx.x * SCAN_B + threadIdx.x;
    int v = (i < N) ? g_deg[i] : 0;
    sm[threadIdx.x] = v;
    __syncthreads();
#pragma unroll
    for (int o = 1; o < SCAN_B; o <<= 1) {
        int t = (threadIdx.x >= o) ? sm[threadIdx.x - o] : 0;
        __syncthreads();
        sm[threadIdx.x] += t;
        __syncthreads();
    }
    if (i < N) g_off[i] = sm[threadIdx.x] - v;   // exclusive
    if (threadIdx.x == SCAN_B - 1) g_bsum[blockIdx.x] = sm[SCAN_B - 1];
}

__global__ void k_scan_sums(int nb) {
    if (threadIdx.x == 0) {
        int acc = 0;
        for (int b = 0; b < nb; b++) { int t = g_bsum[b]; g_bsum[b] = acc; acc += t; }
    }
}

__global__ void k_finalize(int N) {
    int i = blockIdx.x * blockDim.x + threadIdx.x;
    if (i < N) {
        int o = g_off[i] + g_bsum[i / SCAN_B];
        g_off[i] = o;
        g_cur[i] = o;
        g_dis[i] = rsqrtf((float)(g_deg[i] + 1));
    }
}

__global__ void k_fill(const void* __restrict__ ei, int E, int N) {
    int e = blockIdx.x * blockDim.x + threadIdx.x;
    if (e >= E) return;
    int mode = g_mode;
    int s = edge_at(ei, e, mode);
    int d = edge_at(ei, (long long)E + e, mode);
    if (s >= 0 && s < N && d >= 0 && d < N) {
        int pos = atomicAdd(&g_cur[d], 1);
        if (pos >= 0 && pos < E) g_src[pos] = s;
    }
}

// ---------------------------------------------------------------------------
// GEMM (no bias): g_h[set] = fp16( x_set @ W^T )   (fp16 HMMA m16n8k16, f32 acc)
// Block 128(M)x128(N), 8 warps as 2(M)x4(N), warp 64x32.
// W converted+staged ONCE (full K), x streamed in K=16 chunks, double-buffered.
#define GP 68   // W pitch in half2 units: (4g+c)%32 distinct -> conflict-free
#define XP 12   // x pitch in half2 units: (12g+c)%32 distinct -> conflict-free
#define NCHUNK 8  // 128 / 16

__device__ __forceinline__ uint32_t pack_h2(float lo, float hi) {
    __half2 h = __floats2half2_rn(lo, hi);
    return *(uint32_t*)&h;
}

__device__ __forceinline__ void mma_f16(float* d, const uint32_t* a, const uint32_t* b) {
    asm volatile(
        "mma.sync.aligned.m16n8k16.row.col.f32.f16.f16.f32 "
        "{%0,%1,%2,%3}, {%4,%5,%6,%7}, {%8,%9}, {%0,%1,%2,%3};"
        : "+f"(d[0]), "+f"(d[1]), "+f"(d[2]), "+f"(d[3])
        : "r"(a[0]), "r"(a[1]), "r"(a[2]), "r"(a[3]), "r"(b[0]), "r"(b[1]));
}

__global__ void __launch_bounds__(256) k_gemm(
        const float* __restrict__ x0, const float* __restrict__ x1,
        const float* __restrict__ x2, const float* __restrict__ x3,
        const float* __restrict__ W1, const float* __restrict__ W2,
        int N) {
    __shared__ uint32_t Wh[128][GP];      // W[n][k] as half2, full K
    __shared__ uint32_t Xh[2][128][XP];   // x chunk [m][k2], double buffer

    int set = blockIdx.y;
    const float* xp = (set == 0) ? x0 : (set == 1) ? x1 : (set == 2) ? x2 : x3;
    const float* Wp = (set == 0 || set == 2) ? W1 : W2;
    __half* h = g_h + (size_t)set * N * D;

    int tid = threadIdx.x;
    int m0 = blockIdx.x * 128;
    int warp = tid >> 5, lane = tid & 31;
    int wm = warp >> 2, wn = warp & 3;        // 2 x 4 warp grid
    int g = lane >> 2, c = lane & 3;

    // stage full W once: 128 rows x 32 float4
    for (int idx = tid; idx < 128 * 32; idx += 256) {
        int n = idx >> 5, q4 = idx & 31;
        float4 v = *(const float4*)&Wp[n * D + q4 * 4];
        Wh[n][q4 * 2]     = pack_h2(v.x, v.y);
        Wh[n][q4 * 2 + 1] = pack_h2(v.z, v.w);
    }

    // stage x chunk 0: 128 rows x 4 float4 (K=16) -> 512 float4, 2/thread
    int sm_ = tid >> 1;                 // row (2 threads per row)
    int sq = (tid & 1) * 2;             // first of 2 float4 slots
    {
        float4 p[2];
#pragma unroll
        for (int r = 0; r < 2; r++) {
            int gm = m0 + sm_;
            p[r] = make_float4(0.f, 0.f, 0.f, 0.f);
            if (gm < N) p[r] = *(const float4*)&xp[(size_t)gm * D + (sq + r) * 4];
        }
#pragma unroll
        for (int r = 0; r < 2; r++) {
            Xh[0][sm_][(sq + r) * 2]     = pack_h2(p[r].x, p[r].y);
            Xh[0][sm_][(sq + r) * 2 + 1] = pack_h2(p[r].z, p[r].w);
        }
    }
    __syncthreads();

    float acc[4][4][4];
#pragma unroll
    for (int mi = 0; mi < 4; mi++)
#pragma unroll
        for (int ni = 0; ni < 4; ni++)
#pragma unroll
            for (int r = 0; r < 4; r++) acc[mi][ni][r] = 0.0f;

    for (int ck = 0; ck < NCHUNK; ck++) {
        int cur = ck & 1;
        // prefetch next chunk into registers
        float4 p[2];
        if (ck + 1 < NCHUNK) {
            int k0 = (ck + 1) * 16;
            int gm = m0 + sm_;
#pragma unroll
            for (int r = 0; r < 2; r++) {
                p[r] = make_float4(0.f, 0.f, 0.f, 0.f);
                if (gm < N) p[r] = *(const float4*)&xp[(size_t)gm * D + k0 + (sq + r) * 4];
            }
        }

        // compute on current chunk (k2 cols ck*8 .. ck*8+7 of W)
        uint32_t a[4][4], b[4][2];
        int wk = ck * 8;
#pragma unroll
        for (int mi = 0; mi < 4; mi++) {
            int r = wm * 64 + mi * 16 + g;
            a[mi][0] = Xh[cur][r][c];
            a[mi][1] = Xh[cur][r + 8][c];
            a[mi][2] = Xh[cur][r][c + 4];
            a[mi][3] = Xh[cur][r + 8][c + 4];
        }
#pragma unroll
        for (int ni = 0; ni < 4; ni++) {
            int n = wn * 32 + ni * 8 + g;
            b[ni][0] = Wh[n][wk + c];
            b[ni][1] = Wh[n][wk + c + 4];
        }
#pragma unroll
        for (int mi = 0; mi < 4; mi++)
#pragma unroll
            for (int ni = 0; ni < 4; ni++)
                mma_f16(acc[mi][ni], a[mi], b[ni]);

        // store prefetched chunk into other buffer
        if (ck + 1 < NCHUNK) {
#pragma unroll
            for (int r = 0; r < 2; r++) {
                Xh[1 - cur][sm_][(sq + r) * 2]     = pack_h2(p[r].x, p[r].y);
                Xh[1 - cur][sm_][(sq + r) * 2 + 1] = pack_h2(p[r].z, p[r].w);
            }
        }
        __syncthreads();
    }

    // epilogue: convert to fp16, write half2 per fragment pair
#pragma unroll
    for (int ni = 0; ni < 4; ni++) {
        int cb = wn * 32 + ni * 8 + 2 * c;
#pragma unroll
        for (int mi = 0; mi < 4; mi++) {
            int r0 = m0 + wm * 64 + mi * 16 + g;
            int r1 = r0 + 8;
            if (r0 < N)
                *(__half2*)&h[(size_t)r0 * D + cb] =
                    __floats2half2_rn(acc[mi][ni][0], acc[mi][ni][1]);
            if (r1 < N)
                *(__half2*)&h[(size_t)r1 * D + cb] =
                    __floats2half2_rn(acc[mi][ni][2], acc[mi][ni][3]);
        }
    }
}

// ---------------------------------------------------------------------------
// Aggregation: out_s[i] = sum_j norm_ij * h_s[j]  + b_s   (fp32 accumulate)
// One warp per node. Lanes 0-15 handle sets {0,1}, lanes 16-31 sets {2,3};
// each lane owns 8 consecutive columns (one uint4 = 8 halves per set).
__global__ void k_agg(const float* __restrict__ b1, const float* __restrict__ b2,
                      float* __restrict__ out, int N) {
    int gt = blockIdx.x * blockDim.x + threadIdx.x;
    int i = gt >> 5;
    int lane = gt & 31;
    if (i >= N) return;

    int pair = lane >> 4;        // 0 -> sets 0,1 ; 1 -> sets 2,3
    int cp = lane & 15;          // uint4 column index (8 halves)
    int setA = pair * 2;         // 0 or 2  (bias b1)
    int setB = setA + 1;         // 1 or 3  (bias b2)

    const uint4* HA = (const uint4*)(g_h + (size_t)setA * N * D);
    const uint4* HB = (const uint4*)(g_h + (size_t)setB * N * D);

    float di = g_dis[i];
    float d2 = di * di;

    float accA[8], accB[8];
    {   // self-loop term
        uint4 ua = HA[(size_t)i * 16 + cp];
        uint4 ub = HB[(size_t)i * 16 + cp];
        const half2* pa = (const half2*)&ua;
        const half2* pb = (const half2*)&ub;
#pragma unroll
        for (int q = 0; q < 4; q++) {
            float2 fa = __half22float2(pa[q]);
            float2 fb = __half22float2(pb[q]);
            accA[2 * q] = fa.x * d2; accA[2 * q + 1] = fa.y * d2;
            accB[2 * q] = fb.x * d2; accB[2 * q + 1] = fb.y * d2;
        }
    }

    int beg = g_off[i];
    int end = beg + g_deg[i];
    for (int j = beg; j < end; j++) {
        int s = g_src[j];
        float w = di * g_dis[s];
        uint4 ua = HA[(size_t)s * 16 + cp];
        uint4 ub = HB[(size_t)s * 16 + cp];
        const half2* pa = (const half2*)&ua;
        const half2* pb = (const half2*)&ub;
#pragma unroll
        for (int q = 0; q < 4; q++) {
            float2 fa = __half22float2(pa[q]);
            float2 fb = __half22float2(pb[q]);
            accA[2 * q]     = fmaf(fa.x, w, accA[2 * q]);
            accA[2 * q + 1] = fmaf(fa.y, w, accA[2 * q + 1]);
            accB[2 * q]     = fmaf(fb.x, w, accB[2 * q]);
            accB[2 * q + 1] = fmaf(fb.y, w, accB[2 * q + 1]);
        }
    }

    // bias + write
    int col = cp * 8;
    float4 bA0 = *(const float4*)&b1[col];
    float4 bA1 = *(const float4*)&b1[col + 4];
    float4 bB0 = *(const float4*)&b2[col];
    float4 bB1 = *(const float4*)&b2[col + 4];

    float* oA = out + (size_t)setA * N * D + (size_t)i * D + col;
    float* oB = out + (size_t)setB * N * D + (size_t)i * D + col;
    *(float4*)oA       = make_float4(accA[0] + bA0.x, accA[1] + bA0.y,
                                     accA[2] + bA0.z, accA[3] + bA0.w);
    *(float4*)(oA + 4) = make_float4(accA[4] + bA1.x, accA[5] + bA1.y,
                                     accA[6] + bA1.z, accA[7] + bA1.w);
    *(float4*)oB       = make_float4(accB[0] + bB0.x, accB[1] + bB0.y,
                                     accB[2] + bB0.z, accB[3] + bB0.w);
    *(float4*)(oB + 4) = make_float4(accB[4] + bB1.x, accB[5] + bB1.y,
                                     accB[6] + bB1.z, accB[7] + bB1.w);
}

// ---------------------------------------------------------------------------
extern "C" void kernel_launch(void* const* d_in, const int* in_sizes, int n_in,
                              void* d_out, int out_size) {
    const float* x0 = (const float*)d_in[0];  // x_r1 (W1,b1)
    const float* x1 = (const float*)d_in[1];  // x_r2 (W2,b2)
    const float* x2 = (const float*)d_in[2];  // x_i1 (W1,b1)
    const float* x3 = (const float*)d_in[3];  // x_i2 (W2,b2)
    const void*  ei = d_in[4];                // edge_index: int64 OR int32
    const float* W1 = (const float*)d_in[5];
    const float* b1 = (const float*)d_in[6];
    const float* W2 = (const float*)d_in[7];
    const float* b2 = (const float*)d_in[8];
    float* out = (float*)d_out;

    int N = in_sizes[0] / D;
    int E = in_sizes[4] / 2;
    int nb_scan = (N + SCAN_B - 1) / SCAN_B;

    // dtype probe + CSR build + normalization
    k_detect<<<1, 32>>>(ei, E, N);
    k_zero<<<(N + 255) / 256, 256>>>(N);
    k_count<<<(E + 255) / 256, 256>>>(ei, E, N);

    // GEMM first (independent of CSR): h = fp16(x @ W^T), no bias
    {
        dim3 grid((N + 127) / 128, 4);
        k_gemm<<<grid, 256>>>(x0, x1, x2, x3, W1, W2, N);
    }

    k_scan_block<<<nb_scan, SCAN_B>>>(N);
    k_scan_sums<<<1, 32>>>(nb_scan);
    k_finalize<<<(N + 255) / 256, 256>>>(N);
    k_fill<<<(E + 255) / 256, 256>>>(ei, E, N);

    // aggregate fp16 h with fp32 accumulation, add bias, write out
    {
        long long threads = (long long)N * 32;
        int blocks = (int)((threads + 255) / 256);
        k_agg<<<blocks, 256>>>(b1, b2, out, N);
    }
}